// round 9
// baseline (speedup 1.0000x reference)
#include <cuda_runtime.h>
#include <math.h>
#include <stdint.h>

#define NMAX 100000
#define EMAX 1600000
#define HD 128
#define GNUM 64

// ---------------- scratch (device globals: no allocation APIs allowed) ------
__device__ float g_bufA[(size_t)NMAX * HD];   // 51.2 MB
__device__ float g_bufB[(size_t)NMAX * HD];   // 51.2 MB
__device__ int   g_deg[NMAX];
__device__ int   g_local[NMAX];
__device__ int   g_rowptr[NMAX + 1];
__device__ int   g_cursor[NMAX];
__device__ int   g_esrc[EMAX];
__device__ int   g_part[512];
__device__ float g_pool[GNUM * HD];
__device__ float g_zbuf[GNUM * HD];

// ---------------- zero fill --------------------------------------------------
__global__ void zero_f4(float4* __restrict__ p, int n4) {
    int i = blockIdx.x * blockDim.x + threadIdx.x;
    if (i < n4) p[i] = make_float4(0.f, 0.f, 0.f, 0.f);
}

// ---------------- CSR build --------------------------------------------------
__global__ void __launch_bounds__(256) hist_kernel(
    const int* __restrict__ dst, int* __restrict__ deg, int E)
{
    int e = blockIdx.x * blockDim.x + threadIdx.x;
    if (e < E) atomicAdd(&deg[dst[e]], 1);
}

#define SBLK 256
__global__ void __launch_bounds__(SBLK) scan_blocks(
    const int* __restrict__ deg, int* __restrict__ bsum,
    int* __restrict__ local, int n)
{
    __shared__ int sm[SBLK];
    int i = blockIdx.x * SBLK + threadIdx.x;
    int v = (i < n) ? deg[i] : 0;
    sm[threadIdx.x] = v;
    __syncthreads();
    #pragma unroll
    for (int off = 1; off < SBLK; off <<= 1) {
        int t = (threadIdx.x >= off) ? sm[threadIdx.x - off] : 0;
        __syncthreads();
        sm[threadIdx.x] += t;
        __syncthreads();
    }
    if (i < n) local[i] = sm[threadIdx.x] - v;            // exclusive local
    if (threadIdx.x == SBLK - 1) bsum[blockIdx.x] = sm[SBLK - 1];
}

__global__ void __launch_bounds__(512) scan_partials(int* __restrict__ bsum, int nb)
{
    __shared__ int sm[512];
    int v = (threadIdx.x < nb) ? bsum[threadIdx.x] : 0;
    sm[threadIdx.x] = v;
    __syncthreads();
    #pragma unroll
    for (int off = 1; off < 512; off <<= 1) {
        int t = (threadIdx.x >= off) ? sm[threadIdx.x - off] : 0;
        __syncthreads();
        sm[threadIdx.x] += t;
        __syncthreads();
    }
    if (threadIdx.x < nb) bsum[threadIdx.x] = sm[threadIdx.x] - v;  // exclusive
}

__global__ void __launch_bounds__(256) scan_finalize(
    const int* __restrict__ local, const int* __restrict__ bsum,
    int* __restrict__ rowptr, int* __restrict__ cursor, int n, int E)
{
    int i = blockIdx.x * blockDim.x + threadIdx.x;
    if (i < n) {
        int v = local[i] + bsum[i / SBLK];
        rowptr[i] = v;
        cursor[i] = v;
    }
    if (i == 0) rowptr[n] = E;
}

__global__ void __launch_bounds__(256) fill_csr(
    const int* __restrict__ src, const int* __restrict__ dst,
    int* __restrict__ cursor, int* __restrict__ esrc, int E)
{
    int e = blockIdx.x * blockDim.x + threadIdx.x;
    if (e < E) {
        int pos = atomicAdd(&cursor[dst[e]], 1);
        esrc[pos] = src[e];
    }
}

// ============================================================================
// tf32 mma.sync GEMM: Y = X @ W^T + bias.  X:[n,128] f32, W:[128,128] f32.
// CTA: 64 rows x 128 cols, 128 threads (4 warps), warp tile 32x64.
// mma.sync.aligned.m16n8k8.row.col.f32.tf32.tf32.f32
// ============================================================================
#define GS 132                              // smem row stride (floats)
#define GEMM_SMEM ((128 * GS + 64 * GS) * 4)   // W tile + X tile = 101376 B

__device__ __forceinline__ uint32_t f2tf32(float f) {
    uint32_t u;
    asm("cvt.rna.tf32.f32 %0, %1;" : "=r"(u) : "f"(f));
    return u;
}

__global__ void __launch_bounds__(128, 2) gemm_mma(
    const float* __restrict__ X, const float* __restrict__ W,
    const float* __restrict__ bias, float* __restrict__ Y, int n)
{
    extern __shared__ float sm[];
    float* Ws = sm;                 // [128][GS]  (row n of W = output col n)
    float* Xs = sm + 128 * GS;      // [64][GS]
    const int tid  = threadIdx.x;
    const int row0 = blockIdx.x * 64;

    // ---- load W tile (tf32-rounded): 128x32 float4 ----
    const float4* W4 = (const float4*)W;
    #pragma unroll
    for (int i = 0; i < 32; i++) {
        int idx = tid + (i << 7);           // 0..4095
        int r = idx >> 5, c4 = idx & 31;
        float4 v = W4[idx];
        uint4 t = make_uint4(f2tf32(v.x), f2tf32(v.y), f2tf32(v.z), f2tf32(v.w));
        *(uint4*)(Ws + r * GS + c4 * 4) = t;
    }
    // ---- load X tile (tf32-rounded, zero-padded): 64x32 float4 ----
    const float4* X4 = (const float4*)X;
    #pragma unroll
    for (int i = 0; i < 16; i++) {
        int idx = tid + (i << 7);           // 0..2047
        int r = idx >> 5, c4 = idx & 31;
        int gr = row0 + r;
        float4 v = make_float4(0.f, 0.f, 0.f, 0.f);
        if (gr < n) v = X4[(size_t)gr * 32 + c4];
        uint4 t = make_uint4(f2tf32(v.x), f2tf32(v.y), f2tf32(v.z), f2tf32(v.w));
        *(uint4*)(Xs + r * GS + c4 * 4) = t;
    }
    __syncthreads();

    const int wid  = tid >> 5;
    const int lane = tid & 31;
    const int g = lane >> 2;       // group row 0..7
    const int t = lane & 3;        // thread-in-group 0..3
    const int m0 = (wid & 1) * 32;     // warp rows within CTA tile
    const int n0 = (wid >> 1) * 64;    // warp cols

    float acc[2][8][4];
    #pragma unroll
    for (int mt = 0; mt < 2; mt++)
        #pragma unroll
        for (int j = 0; j < 8; j++)
            #pragma unroll
            for (int q = 0; q < 4; q++) acc[mt][j][q] = 0.f;

    #pragma unroll
    for (int s = 0; s < 16; s++) {
        const int k0 = s << 3;
        uint32_t a[2][4];
        #pragma unroll
        for (int mt = 0; mt < 2; mt++) {
            const float* base = Xs + (m0 + mt * 16 + g) * GS + k0 + t;
            a[mt][0] = *(const uint32_t*)(base);
            a[mt][1] = *(const uint32_t*)(base + 8 * GS);
            a[mt][2] = *(const uint32_t*)(base + 4);
            a[mt][3] = *(const uint32_t*)(base + 8 * GS + 4);
        }
        #pragma unroll
        for (int j = 0; j < 8; j++) {
            const float* wb = Ws + (n0 + j * 8 + g) * GS + k0 + t;
            uint32_t b0 = *(const uint32_t*)(wb);
            uint32_t b1 = *(const uint32_t*)(wb + 4);
            #pragma unroll
            for (int mt = 0; mt < 2; mt++) {
                asm volatile(
                    "mma.sync.aligned.m16n8k8.row.col.f32.tf32.tf32.f32 "
                    "{%0,%1,%2,%3}, {%4,%5,%6,%7}, {%8,%9}, {%0,%1,%2,%3};"
                    : "+f"(acc[mt][j][0]), "+f"(acc[mt][j][1]),
                      "+f"(acc[mt][j][2]), "+f"(acc[mt][j][3])
                    : "r"(a[mt][0]), "r"(a[mt][1]), "r"(a[mt][2]), "r"(a[mt][3]),
                      "r"(b0), "r"(b1));
            }
        }
    }

    // ---- epilogue: c0/c1 at (g, 2t..2t+1), c2/c3 at (g+8, ...) ----
    #pragma unroll
    for (int mt = 0; mt < 2; mt++) {
        int r_lo = row0 + m0 + mt * 16 + g;
        int r_hi = r_lo + 8;
        #pragma unroll
        for (int j = 0; j < 8; j++) {
            int c = n0 + j * 8 + 2 * t;
            float2 bv = *(const float2*)&bias[c];
            if (r_lo < n) {
                float2 o = make_float2(acc[mt][j][0] + bv.x, acc[mt][j][1] + bv.y);
                *(float2*)(Y + (size_t)r_lo * HD + c) = o;
            }
            if (r_hi < n) {
                float2 o = make_float2(acc[mt][j][2] + bv.x, acc[mt][j][3] + bv.y);
                *(float2*)(Y + (size_t)r_hi * HD + c) = o;
            }
        }
    }
}

// ---------------- gather aggregation: out[v] = relu(mean_{e->v} xw[src(e)]) --
__global__ void __launch_bounds__(256) gather_mean_relu(
    const float* __restrict__ xw, const int* __restrict__ rp,
    const int* __restrict__ esrc, float* __restrict__ out, int n)
{
    int gw = (blockIdx.x * blockDim.x + threadIdx.x) >> 5;
    if (gw >= n) return;
    int lane = threadIdx.x & 31;
    int a = __ldg(&rp[gw]);
    int b = __ldg(&rp[gw + 1]);

    float4 acc = make_float4(0.f, 0.f, 0.f, 0.f);
    const float4* xw4 = (const float4*)xw;
    int e = a;
    for (; e + 4 <= b; e += 4) {
        int s0 = __ldg(&esrc[e]);
        int s1 = __ldg(&esrc[e + 1]);
        int s2 = __ldg(&esrc[e + 2]);
        int s3 = __ldg(&esrc[e + 3]);
        float4 v0 = __ldg(xw4 + (size_t)s0 * 32 + lane);
        float4 v1 = __ldg(xw4 + (size_t)s1 * 32 + lane);
        float4 v2 = __ldg(xw4 + (size_t)s2 * 32 + lane);
        float4 v3 = __ldg(xw4 + (size_t)s3 * 32 + lane);
        acc.x += v0.x + v1.x + v2.x + v3.x;
        acc.y += v0.y + v1.y + v2.y + v3.y;
        acc.z += v0.z + v1.z + v2.z + v3.z;
        acc.w += v0.w + v1.w + v2.w + v3.w;
    }
    for (; e < b; e++) {
        int s = __ldg(&esrc[e]);
        float4 v = __ldg(xw4 + (size_t)s * 32 + lane);
        acc.x += v.x; acc.y += v.y; acc.z += v.z; acc.w += v.w;
    }

    float inv = (b > a) ? 1.0f / (float)(b - a) : 0.0f;
    acc.x = fmaxf(acc.x * inv, 0.f);
    acc.y = fmaxf(acc.y * inv, 0.f);
    acc.z = fmaxf(acc.z * inv, 0.f);
    acc.w = fmaxf(acc.w * inv, 0.f);
    ((float4*)out)[(size_t)gw * 32 + lane] = acc;
}

// ---------------- segment_max pool (batch is sorted) -------------------------
__global__ void __launch_bounds__(128) pool_kernel(
    const float* __restrict__ h, const int* __restrict__ batch,
    float* __restrict__ pool, int n)
{
    const int NPB = 128;
    int n0 = blockIdx.x * NPB;
    if (n0 >= n) return;
    int nend = min(n0 + NPB, n);
    int c = threadIdx.x;
    int curb = batch[n0];
    float m = 0.0f;
    for (int nn = n0; nn < nend; nn++) {
        int b = batch[nn];
        if (b != curb) {
            atomicMax((int*)&pool[curb * HD + c], __float_as_int(m));
            m = 0.0f;
            curb = b;
        }
        m = fmaxf(m, h[(size_t)nn * HD + c]);
    }
    atomicMax((int*)&pool[curb * HD + c], __float_as_int(m));
}

// ---------------- FC head ----------------------------------------------------
__global__ void __launch_bounds__(128) fc1_kernel(
    const float* __restrict__ pool, const float* __restrict__ Wf1,
    const float* __restrict__ bf1, float* __restrict__ z)
{
    __shared__ float gv[HD];
    int g = blockIdx.x;
    gv[threadIdx.x] = pool[g * HD + threadIdx.x];
    __syncthreads();
    const float* w = Wf1 + threadIdx.x * HD;
    float acc = 0.f;
    #pragma unroll 16
    for (int k = 0; k < HD; k++) acc += gv[k] * w[k];
    z[g * HD + threadIdx.x] = fmaxf(acc + bf1[threadIdx.x], 0.f);
}

__global__ void __launch_bounds__(64) fc2_kernel(
    const float* __restrict__ z, const float* __restrict__ Wf2,
    const float* __restrict__ bf2, float* __restrict__ out)
{
    int g = threadIdx.x;
    if (g >= GNUM) return;
    float a0 = bf2[0], a1 = bf2[1];
    #pragma unroll 16
    for (int k = 0; k < HD; k++) {
        float v = z[g * HD + k];
        a0 += v * Wf2[k];
        a1 += v * Wf2[HD + k];
    }
    float m   = fmaxf(a0, a1);
    float lse = m + logf(expf(a0 - m) + expf(a1 - m));
    out[g * 2 + 0] = a0 - lse;
    out[g * 2 + 1] = a1 - lse;
}

// ---------------- launch -----------------------------------------------------
extern "C" void kernel_launch(void* const* d_in, const int* in_sizes, int n_in,
                              void* d_out, int out_size)
{
    const float* x     = (const float*)d_in[0];
    const int*   ei    = (const int*)d_in[1];
    const int*   batch = (const int*)d_in[2];
    const float* W1    = (const float*)d_in[3];
    const float* b1    = (const float*)d_in[4];
    const float* W2    = (const float*)d_in[5];
    const float* b2    = (const float*)d_in[6];
    const float* Wf1   = (const float*)d_in[7];
    const float* bf1   = (const float*)d_in[8];
    const float* Wf2   = (const float*)d_in[9];
    const float* bf2   = (const float*)d_in[10];

    const int n = in_sizes[0] / HD;        // 100000
    const int E = in_sizes[1] / 2;         // 1600000
    const int* src = ei;
    const int* dst = ei + E;

    float *bufA, *bufB, *pool, *zb;
    int *deg, *local, *rowptr, *cursor, *esrc, *part;
    cudaGetSymbolAddress((void**)&bufA,   g_bufA);
    cudaGetSymbolAddress((void**)&bufB,   g_bufB);
    cudaGetSymbolAddress((void**)&deg,    g_deg);
    cudaGetSymbolAddress((void**)&local,  g_local);
    cudaGetSymbolAddress((void**)&rowptr, g_rowptr);
    cudaGetSymbolAddress((void**)&cursor, g_cursor);
    cudaGetSymbolAddress((void**)&esrc,   g_esrc);
    cudaGetSymbolAddress((void**)&part,   g_part);
    cudaGetSymbolAddress((void**)&pool,   g_pool);
    cudaGetSymbolAddress((void**)&zb,     g_zbuf);

    cudaFuncSetAttribute(gemm_mma, cudaFuncAttributeMaxDynamicSharedMemorySize,
                         GEMM_SMEM);

    const int gemm_blocks   = (n + 63) / 64;
    const int gather_blocks = (n * 32 + 255) / 256;   // warp per node
    const int eblocks       = (E + 255) / 256;
    const int nscan_blocks  = (n + SBLK - 1) / SBLK;  // 391

    // ---- CSR build (once; reused by both layers) ----
    zero_f4<<<(n / 4 + 255) / 256, 256>>>((float4*)deg, n / 4);
    hist_kernel<<<eblocks, 256>>>(dst, deg, E);
    scan_blocks<<<nscan_blocks, SBLK>>>(deg, part, local, n);
    scan_partials<<<1, 512>>>(part, nscan_blocks);
    scan_finalize<<<(n + 255) / 256, 256>>>(local, part, rowptr, cursor, n, E);
    fill_csr<<<eblocks, 256>>>(src, dst, cursor, esrc, E);

    // ---- layer 1 ----
    gemm_mma<<<gemm_blocks, 128, GEMM_SMEM>>>(x, W1, b1, bufA, n);
    gather_mean_relu<<<gather_blocks, 256>>>(bufA, rowptr, esrc, bufB, n);

    // ---- layer 2 ----
    gemm_mma<<<gemm_blocks, 128, GEMM_SMEM>>>(bufB, W2, b2, bufA, n);
    gather_mean_relu<<<gather_blocks, 256>>>(bufA, rowptr, esrc, bufB, n);

    // ---- pool + head ----
    zero_f4<<<(GNUM * HD / 4 + 255) / 256, 256>>>((float4*)pool, GNUM * HD / 4);
    pool_kernel<<<(n + 127) / 128, 128>>>(bufB, batch, pool, n);
    fc1_kernel<<<GNUM, 128>>>(pool, Wf1, bf1, zb);
    fc2_kernel<<<1, 64>>>(zb, Wf2, bf2, (float*)d_out);
}

// round 10
// speedup vs baseline: 1.1485x; 1.1485x over previous
#include <cuda_runtime.h>
#include <cuda_fp16.h>
#include <math.h>
#include <stdint.h>

#define NMAX 100000
#define EMAX 1600000
#define HD 128
#define GNUM 64

// ---------------- scratch (device globals: no allocation APIs allowed) ------
__device__ float g_bufA[(size_t)NMAX * HD / 2];   // used as __half[N*HD]
__device__ float g_bufB[(size_t)NMAX * HD / 2];   // used as __half[N*HD]
__device__ int   g_deg[NMAX];
__device__ int   g_local[NMAX];
__device__ int   g_rowptr[NMAX + 1];
__device__ int   g_cursor[NMAX];
__device__ int   g_esrc[EMAX];
__device__ int   g_part[512];
__device__ float g_pool[GNUM * HD];
__device__ float g_zbuf[GNUM * HD];

// ---------------- zero fill --------------------------------------------------
__global__ void zero_f4(float4* __restrict__ p, int n4) {
    int i = blockIdx.x * blockDim.x + threadIdx.x;
    if (i < n4) p[i] = make_float4(0.f, 0.f, 0.f, 0.f);
}

// ---------------- CSR build --------------------------------------------------
__global__ void __launch_bounds__(256) hist_kernel(
    const int* __restrict__ dst, int* __restrict__ deg, int E)
{
    int e = blockIdx.x * blockDim.x + threadIdx.x;
    if (e < E) atomicAdd(&deg[dst[e]], 1);
}

#define SBLK 256
__global__ void __launch_bounds__(SBLK) scan_blocks(
    const int* __restrict__ deg, int* __restrict__ bsum,
    int* __restrict__ local, int n)
{
    __shared__ int sm[SBLK];
    int i = blockIdx.x * SBLK + threadIdx.x;
    int v = (i < n) ? deg[i] : 0;
    sm[threadIdx.x] = v;
    __syncthreads();
    #pragma unroll
    for (int off = 1; off < SBLK; off <<= 1) {
        int t = (threadIdx.x >= off) ? sm[threadIdx.x - off] : 0;
        __syncthreads();
        sm[threadIdx.x] += t;
        __syncthreads();
    }
    if (i < n) local[i] = sm[threadIdx.x] - v;            // exclusive local
    if (threadIdx.x == SBLK - 1) bsum[blockIdx.x] = sm[SBLK - 1];
}

__global__ void __launch_bounds__(512) scan_partials(int* __restrict__ bsum, int nb)
{
    __shared__ int sm[512];
    int v = (threadIdx.x < nb) ? bsum[threadIdx.x] : 0;
    sm[threadIdx.x] = v;
    __syncthreads();
    #pragma unroll
    for (int off = 1; off < 512; off <<= 1) {
        int t = (threadIdx.x >= off) ? sm[threadIdx.x - off] : 0;
        __syncthreads();
        sm[threadIdx.x] += t;
        __syncthreads();
    }
    if (threadIdx.x < nb) bsum[threadIdx.x] = sm[threadIdx.x] - v;  // exclusive
}

__global__ void __launch_bounds__(256) scan_finalize(
    const int* __restrict__ local, const int* __restrict__ bsum,
    int* __restrict__ rowptr, int* __restrict__ cursor, int n, int E)
{
    int i = blockIdx.x * blockDim.x + threadIdx.x;
    if (i < n) {
        int v = local[i] + bsum[i / SBLK];
        rowptr[i] = v;
        cursor[i] = v;
    }
    if (i == 0) rowptr[n] = E;
}

__global__ void __launch_bounds__(256) fill_csr(
    const int* __restrict__ src, const int* __restrict__ dst,
    int* __restrict__ cursor, int* __restrict__ esrc, int E)
{
    int e = blockIdx.x * blockDim.x + threadIdx.x;
    if (e < E) {
        int pos = atomicAdd(&cursor[dst[e]], 1);
        esrc[pos] = src[e];
    }
}

// ============================================================================
// tf32 mma.sync GEMM: Y = X @ W^T + bias.  X:[n,128] (f32 or f16), W f32.
// Output: __half [n,128].
// CTA: 64 rows x 128 cols, 128 threads (4 warps), warp tile 32x64.
// ============================================================================
#define GS 132                              // smem row stride (floats)
#define GEMM_SMEM ((128 * GS + 64 * GS) * 4)   // W tile + X tile = 101376 B

__device__ __forceinline__ uint32_t f2tf32(float f) {
    uint32_t u;
    asm("cvt.rna.tf32.f32 %0, %1;" : "=r"(u) : "f"(f));
    return u;
}

template<bool HALF_IN>
__global__ void __launch_bounds__(128, 2) gemm_mma(
    const void* __restrict__ Xv, const float* __restrict__ W,
    const float* __restrict__ bias, __half* __restrict__ Y, int n)
{
    extern __shared__ float sm[];
    float* Ws = sm;                 // [128][GS]  (row n of W = output col n)
    float* Xs = sm + 128 * GS;      // [64][GS]
    const int tid  = threadIdx.x;
    const int row0 = blockIdx.x * 64;

    // ---- load W tile (tf32-rounded): 128x32 float4 ----
    const float4* W4 = (const float4*)W;
    #pragma unroll
    for (int i = 0; i < 32; i++) {
        int idx = tid + (i << 7);           // 0..4095
        int r = idx >> 5, c4 = idx & 31;
        float4 v = W4[idx];
        uint4 t = make_uint4(f2tf32(v.x), f2tf32(v.y), f2tf32(v.z), f2tf32(v.w));
        *(uint4*)(Ws + r * GS + c4 * 4) = t;
    }
    // ---- load X tile (tf32-rounded, zero-padded) ----
    if (HALF_IN) {
        const uint4* X8 = (const uint4*)Xv;       // 16B = 8 halfs
        #pragma unroll
        for (int i = 0; i < 8; i++) {
            int idx = tid + (i << 7);             // 0..1023
            int r = idx >> 4, c8 = idx & 15;      // row, 8-col chunk
            int gr = row0 + r;
            uint4 u = make_uint4(0, 0, 0, 0);
            if (gr < n) u = X8[(size_t)gr * 16 + c8];
            const __half2* h2 = (const __half2*)&u;
            uint32_t t[8];
            #pragma unroll
            for (int q = 0; q < 4; q++) {
                float2 f = __half22float2(h2[q]);
                t[2 * q]     = f2tf32(f.x);
                t[2 * q + 1] = f2tf32(f.y);
            }
            float* dstp = Xs + r * GS + c8 * 8;
            *(uint4*)(dstp)     = *(uint4*)&t[0];
            *(uint4*)(dstp + 4) = *(uint4*)&t[4];
        }
    } else {
        const float4* X4 = (const float4*)Xv;
        #pragma unroll
        for (int i = 0; i < 16; i++) {
            int idx = tid + (i << 7);           // 0..2047
            int r = idx >> 5, c4 = idx & 31;
            int gr = row0 + r;
            float4 v = make_float4(0.f, 0.f, 0.f, 0.f);
            if (gr < n) v = X4[(size_t)gr * 32 + c4];
            uint4 t = make_uint4(f2tf32(v.x), f2tf32(v.y), f2tf32(v.z), f2tf32(v.w));
            *(uint4*)(Xs + r * GS + c4 * 4) = t;
        }
    }
    __syncthreads();

    const int wid  = tid >> 5;
    const int lane = tid & 31;
    const int g = lane >> 2;       // group row 0..7
    const int t = lane & 3;        // thread-in-group 0..3
    const int m0 = (wid & 1) * 32;     // warp rows within CTA tile
    const int n0 = (wid >> 1) * 64;    // warp cols

    float acc[2][8][4];
    #pragma unroll
    for (int mt = 0; mt < 2; mt++)
        #pragma unroll
        for (int j = 0; j < 8; j++)
            #pragma unroll
            for (int q = 0; q < 4; q++) acc[mt][j][q] = 0.f;

    #pragma unroll
    for (int s = 0; s < 16; s++) {
        const int k0 = s << 3;
        uint32_t a[2][4];
        #pragma unroll
        for (int mt = 0; mt < 2; mt++) {
            const float* base = Xs + (m0 + mt * 16 + g) * GS + k0 + t;
            a[mt][0] = *(const uint32_t*)(base);
            a[mt][1] = *(const uint32_t*)(base + 8 * GS);
            a[mt][2] = *(const uint32_t*)(base + 4);
            a[mt][3] = *(const uint32_t*)(base + 8 * GS + 4);
        }
        #pragma unroll
        for (int j = 0; j < 8; j++) {
            const float* wb = Ws + (n0 + j * 8 + g) * GS + k0 + t;
            uint32_t b0 = *(const uint32_t*)(wb);
            uint32_t b1 = *(const uint32_t*)(wb + 4);
            #pragma unroll
            for (int mt = 0; mt < 2; mt++) {
                asm volatile(
                    "mma.sync.aligned.m16n8k8.row.col.f32.tf32.tf32.f32 "
                    "{%0,%1,%2,%3}, {%4,%5,%6,%7}, {%8,%9}, {%0,%1,%2,%3};"
                    : "+f"(acc[mt][j][0]), "+f"(acc[mt][j][1]),
                      "+f"(acc[mt][j][2]), "+f"(acc[mt][j][3])
                    : "r"(a[mt][0]), "r"(a[mt][1]), "r"(a[mt][2]), "r"(a[mt][3]),
                      "r"(b0), "r"(b1));
            }
        }
    }

    // ---- epilogue: half2 stores. c0/c1 at (g, 2t), c2/c3 at (g+8, 2t) ----
    #pragma unroll
    for (int mt = 0; mt < 2; mt++) {
        int r_lo = row0 + m0 + mt * 16 + g;
        int r_hi = r_lo + 8;
        #pragma unroll
        for (int j = 0; j < 8; j++) {
            int c = n0 + j * 8 + 2 * t;
            float2 bv = *(const float2*)&bias[c];
            if (r_lo < n) {
                __half2 o = __floats2half2_rn(acc[mt][j][0] + bv.x,
                                              acc[mt][j][1] + bv.y);
                *(__half2*)(Y + (size_t)r_lo * HD + c) = o;
            }
            if (r_hi < n) {
                __half2 o = __floats2half2_rn(acc[mt][j][2] + bv.x,
                                              acc[mt][j][3] + bv.y);
                *(__half2*)(Y + (size_t)r_hi * HD + c) = o;
            }
        }
    }
}

// ---------------- gather: out[v] = relu(mean_{e->v} xw[src(e)])  (fp16 I/O) --
// One warp per node. Lane handles 4 cols (one uint2 = 4 halfs). Row = 256B.
__global__ void __launch_bounds__(256) gather_mean_relu(
    const __half* __restrict__ xw, const int* __restrict__ rp,
    const int* __restrict__ esrc, __half* __restrict__ out, int n)
{
    int gw = (blockIdx.x * blockDim.x + threadIdx.x) >> 5;
    if (gw >= n) return;
    int lane = threadIdx.x & 31;
    int a = __ldg(&rp[gw]);
    int b = __ldg(&rp[gw + 1]);

    float4 acc = make_float4(0.f, 0.f, 0.f, 0.f);
    const uint2* xw2 = (const uint2*)xw;          // row = 32 uint2
    int e = a;
    for (; e + 4 <= b; e += 4) {
        int s0 = __ldg(&esrc[e]);
        int s1 = __ldg(&esrc[e + 1]);
        int s2 = __ldg(&esrc[e + 2]);
        int s3 = __ldg(&esrc[e + 3]);
        uint2 u0 = __ldg(xw2 + (size_t)s0 * 32 + lane);
        uint2 u1 = __ldg(xw2 + (size_t)s1 * 32 + lane);
        uint2 u2 = __ldg(xw2 + (size_t)s2 * 32 + lane);
        uint2 u3 = __ldg(xw2 + (size_t)s3 * 32 + lane);
        #pragma unroll
        for (int q = 0; q < 4; q++) {
            uint2 u = (q == 0) ? u0 : (q == 1) ? u1 : (q == 2) ? u2 : u3;
            float2 lo = __half22float2(*(__half2*)&u.x);
            float2 hi = __half22float2(*(__half2*)&u.y);
            acc.x += lo.x; acc.y += lo.y; acc.z += hi.x; acc.w += hi.y;
        }
    }
    for (; e < b; e++) {
        int s = __ldg(&esrc[e]);
        uint2 u = __ldg(xw2 + (size_t)s * 32 + lane);
        float2 lo = __half22float2(*(__half2*)&u.x);
        float2 hi = __half22float2(*(__half2*)&u.y);
        acc.x += lo.x; acc.y += lo.y; acc.z += hi.x; acc.w += hi.y;
    }

    float inv = (b > a) ? 1.0f / (float)(b - a) : 0.0f;
    __half2 o0 = __floats2half2_rn(fmaxf(acc.x * inv, 0.f), fmaxf(acc.y * inv, 0.f));
    __half2 o1 = __floats2half2_rn(fmaxf(acc.z * inv, 0.f), fmaxf(acc.w * inv, 0.f));
    uint2 ou;
    *(__half2*)&ou.x = o0;
    *(__half2*)&ou.y = o1;
    ((uint2*)out)[(size_t)gw * 32 + lane] = ou;
}

// ---------------- segment_max pool (batch is sorted, h is fp16) --------------
__global__ void __launch_bounds__(128) pool_kernel(
    const __half* __restrict__ h, const int* __restrict__ batch,
    float* __restrict__ pool, int n)
{
    const int NPB = 128;
    int n0 = blockIdx.x * NPB;
    if (n0 >= n) return;
    int nend = min(n0 + NPB, n);
    int c = threadIdx.x;
    int curb = batch[n0];
    float m = 0.0f;
    for (int nn = n0; nn < nend; nn++) {
        int b = batch[nn];
        if (b != curb) {
            atomicMax((int*)&pool[curb * HD + c], __float_as_int(m));
            m = 0.0f;
            curb = b;
        }
        m = fmaxf(m, __half2float(h[(size_t)nn * HD + c]));
    }
    atomicMax((int*)&pool[curb * HD + c], __float_as_int(m));
}

// ---------------- FC head ----------------------------------------------------
__global__ void __launch_bounds__(128) fc1_kernel(
    const float* __restrict__ pool, const float* __restrict__ Wf1,
    const float* __restrict__ bf1, float* __restrict__ z)
{
    __shared__ float gv[HD];
    int g = blockIdx.x;
    gv[threadIdx.x] = pool[g * HD + threadIdx.x];
    __syncthreads();
    const float* w = Wf1 + threadIdx.x * HD;
    float acc = 0.f;
    #pragma unroll 16
    for (int k = 0; k < HD; k++) acc += gv[k] * w[k];
    z[g * HD + threadIdx.x] = fmaxf(acc + bf1[threadIdx.x], 0.f);
}

__global__ void __launch_bounds__(64) fc2_kernel(
    const float* __restrict__ z, const float* __restrict__ Wf2,
    const float* __restrict__ bf2, float* __restrict__ out)
{
    int g = threadIdx.x;
    if (g >= GNUM) return;
    float a0 = bf2[0], a1 = bf2[1];
    #pragma unroll 16
    for (int k = 0; k < HD; k++) {
        float v = z[g * HD + k];
        a0 += v * Wf2[k];
        a1 += v * Wf2[HD + k];
    }
    float m   = fmaxf(a0, a1);
    float lse = m + logf(expf(a0 - m) + expf(a1 - m));
    out[g * 2 + 0] = a0 - lse;
    out[g * 2 + 1] = a1 - lse;
}

// ---------------- launch -----------------------------------------------------
extern "C" void kernel_launch(void* const* d_in, const int* in_sizes, int n_in,
                              void* d_out, int out_size)
{
    const float* x     = (const float*)d_in[0];
    const int*   ei    = (const int*)d_in[1];
    const int*   batch = (const int*)d_in[2];
    const float* W1    = (const float*)d_in[3];
    const float* b1    = (const float*)d_in[4];
    const float* W2    = (const float*)d_in[5];
    const float* b2    = (const float*)d_in[6];
    const float* Wf1   = (const float*)d_in[7];
    const float* bf1   = (const float*)d_in[8];
    const float* Wf2   = (const float*)d_in[9];
    const float* bf2   = (const float*)d_in[10];

    const int n = in_sizes[0] / HD;        // 100000
    const int E = in_sizes[1] / 2;         // 1600000
    const int* src = ei;
    const int* dst = ei + E;

    __half *bufA, *bufB;
    float *pool, *zb;
    int *deg, *local, *rowptr, *cursor, *esrc, *part;
    cudaGetSymbolAddress((void**)&bufA,   g_bufA);
    cudaGetSymbolAddress((void**)&bufB,   g_bufB);
    cudaGetSymbolAddress((void**)&deg,    g_deg);
    cudaGetSymbolAddress((void**)&local,  g_local);
    cudaGetSymbolAddress((void**)&rowptr, g_rowptr);
    cudaGetSymbolAddress((void**)&cursor, g_cursor);
    cudaGetSymbolAddress((void**)&esrc,   g_esrc);
    cudaGetSymbolAddress((void**)&part,   g_part);
    cudaGetSymbolAddress((void**)&pool,   g_pool);
    cudaGetSymbolAddress((void**)&zb,     g_zbuf);

    cudaFuncSetAttribute(gemm_mma<false>,
                         cudaFuncAttributeMaxDynamicSharedMemorySize, GEMM_SMEM);
    cudaFuncSetAttribute(gemm_mma<true>,
                         cudaFuncAttributeMaxDynamicSharedMemorySize, GEMM_SMEM);

    const int gemm_blocks   = (n + 63) / 64;
    const int gather_blocks = (n * 32 + 255) / 256;   // warp per node
    const int eblocks       = (E + 255) / 256;
    const int nscan_blocks  = (n + SBLK - 1) / SBLK;  // 391

    // ---- CSR build (once; reused by both layers) ----
    zero_f4<<<(n / 4 + 255) / 256, 256>>>((float4*)deg, n / 4);
    hist_kernel<<<eblocks, 256>>>(dst, deg, E);
    scan_blocks<<<nscan_blocks, SBLK>>>(deg, part, local, n);
    scan_partials<<<1, 512>>>(part, nscan_blocks);
    scan_finalize<<<(n + 255) / 256, 256>>>(local, part, rowptr, cursor, n, E);
    fill_csr<<<eblocks, 256>>>(src, dst, cursor, esrc, E);

    // ---- layer 1 ----
    gemm_mma<false><<<gemm_blocks, 128, GEMM_SMEM>>>(x, W1, b1, bufA, n);
    gather_mean_relu<<<gather_blocks, 256>>>(bufA, rowptr, esrc, bufB, n);

    // ---- layer 2 ----
    gemm_mma<true><<<gemm_blocks, 128, GEMM_SMEM>>>(bufB, W2, b2, bufA, n);
    gather_mean_relu<<<gather_blocks, 256>>>(bufA, rowptr, esrc, bufB, n);

    // ---- pool + head ----
    zero_f4<<<(GNUM * HD / 4 + 255) / 256, 256>>>((float4*)pool, GNUM * HD / 4);
    pool_kernel<<<(n + 127) / 128, 128>>>(bufB, batch, pool, n);
    fc1_kernel<<<GNUM, 128>>>(pool, Wf1, bf1, zb);
    fc2_kernel<<<1, 64>>>(zb, Wf2, bf2, (float*)d_out);
}

// round 11
// speedup vs baseline: 1.1520x; 1.0031x over previous
#include <cuda_runtime.h>
#include <cuda_fp16.h>
#include <math.h>
#include <stdint.h>

#define NMAX 100000
#define EMAX 1600000
#define HD 128
#define GNUM 64

// ---------------- scratch (device globals: no allocation APIs allowed) ------
__device__ float g_bufA[(size_t)NMAX * HD / 2];   // used as __half[N*HD]
__device__ float g_bufB[(size_t)NMAX * HD / 2];   // used as __half[N*HD]
__device__ int   g_deg[NMAX];
__device__ int   g_local[NMAX];
__device__ int   g_rowptr[NMAX + 1];
__device__ int   g_cursor[NMAX];
__device__ int   g_esrc[EMAX];
__device__ int   g_part[512];
__device__ float g_pool[GNUM * HD];
__device__ float g_zbuf[GNUM * HD];

// ---------------- zero fill --------------------------------------------------
__global__ void zero_f4(float4* __restrict__ p, int n4) {
    int i = blockIdx.x * blockDim.x + threadIdx.x;
    if (i < n4) p[i] = make_float4(0.f, 0.f, 0.f, 0.f);
}

// ---------------- CSR build --------------------------------------------------
__global__ void __launch_bounds__(256) hist_kernel(
    const int* __restrict__ dst, int* __restrict__ deg, int E)
{
    int e = blockIdx.x * blockDim.x + threadIdx.x;
    if (e < E) atomicAdd(&deg[dst[e]], 1);
}

#define SBLK 256
__global__ void __launch_bounds__(SBLK) scan_blocks(
    const int* __restrict__ deg, int* __restrict__ bsum,
    int* __restrict__ local, int n)
{
    __shared__ int sm[SBLK];
    int i = blockIdx.x * SBLK + threadIdx.x;
    int v = (i < n) ? deg[i] : 0;
    sm[threadIdx.x] = v;
    __syncthreads();
    #pragma unroll
    for (int off = 1; off < SBLK; off <<= 1) {
        int t = (threadIdx.x >= off) ? sm[threadIdx.x - off] : 0;
        __syncthreads();
        sm[threadIdx.x] += t;
        __syncthreads();
    }
    if (i < n) local[i] = sm[threadIdx.x] - v;            // exclusive local
    if (threadIdx.x == SBLK - 1) bsum[blockIdx.x] = sm[SBLK - 1];
}

__global__ void __launch_bounds__(512) scan_partials(int* __restrict__ bsum, int nb)
{
    __shared__ int sm[512];
    int v = (threadIdx.x < nb) ? bsum[threadIdx.x] : 0;
    sm[threadIdx.x] = v;
    __syncthreads();
    #pragma unroll
    for (int off = 1; off < 512; off <<= 1) {
        int t = (threadIdx.x >= off) ? sm[threadIdx.x - off] : 0;
        __syncthreads();
        sm[threadIdx.x] += t;
        __syncthreads();
    }
    if (threadIdx.x < nb) bsum[threadIdx.x] = sm[threadIdx.x] - v;  // exclusive
}

__global__ void __launch_bounds__(256) scan_finalize(
    const int* __restrict__ local, const int* __restrict__ bsum,
    int* __restrict__ rowptr, int* __restrict__ cursor, int n, int E)
{
    int i = blockIdx.x * blockDim.x + threadIdx.x;
    if (i < n) {
        int v = local[i] + bsum[i / SBLK];
        rowptr[i] = v;
        cursor[i] = v;
    }
    if (i == 0) rowptr[n] = E;
}

__global__ void __launch_bounds__(256) fill_csr(
    const int* __restrict__ src, const int* __restrict__ dst,
    int* __restrict__ cursor, int* __restrict__ esrc, int E)
{
    int e = blockIdx.x * blockDim.x + threadIdx.x;
    if (e < E) {
        int pos = atomicAdd(&cursor[dst[e]], 1);
        esrc[pos] = src[e];
    }
}

// ============================================================================
// tf32 mma.sync GEMM: Y = X @ W^T + bias.  X:[n,128] (f32 or f16), W f32.
// Output: __half [n,128].
// CTA: 64 rows x 128 cols, 128 threads (4 warps), warp tile 32x64.
// ============================================================================
#define GS 132                              // smem row stride (floats)
#define GEMM_SMEM ((128 * GS + 64 * GS) * 4)   // W tile + X tile = 101376 B

__device__ __forceinline__ uint32_t f2tf32(float f) {
    uint32_t u;
    asm("cvt.rna.tf32.f32 %0, %1;" : "=r"(u) : "f"(f));
    return u;
}

template<bool HALF_IN>
__global__ void __launch_bounds__(128, 2) gemm_mma(
    const void* __restrict__ Xv, const float* __restrict__ W,
    const float* __restrict__ bias, __half* __restrict__ Y, int n)
{
    extern __shared__ float sm[];
    float* Ws = sm;                 // [128][GS]  (row n of W = output col n)
    float* Xs = sm + 128 * GS;      // [64][GS]
    const int tid  = threadIdx.x;
    const int row0 = blockIdx.x * 64;

    // ---- load W tile (tf32-rounded): 128x32 float4 ----
    const float4* W4 = (const float4*)W;
    #pragma unroll
    for (int i = 0; i < 32; i++) {
        int idx = tid + (i << 7);           // 0..4095
        int r = idx >> 5, c4 = idx & 31;
        float4 v = W4[idx];
        uint4 t = make_uint4(f2tf32(v.x), f2tf32(v.y), f2tf32(v.z), f2tf32(v.w));
        *(uint4*)(Ws + r * GS + c4 * 4) = t;
    }
    // ---- load X tile (tf32-rounded, zero-padded) ----
    if (HALF_IN) {
        const uint4* X8 = (const uint4*)Xv;       // 16B = 8 halfs
        #pragma unroll
        for (int i = 0; i < 8; i++) {
            int idx = tid + (i << 7);             // 0..1023
            int r = idx >> 4, c8 = idx & 15;      // row, 8-col chunk
            int gr = row0 + r;
            uint4 u = make_uint4(0, 0, 0, 0);
            if (gr < n) u = X8[(size_t)gr * 16 + c8];
            const __half2* h2 = (const __half2*)&u;
            uint32_t t[8];
            #pragma unroll
            for (int q = 0; q < 4; q++) {
                float2 f = __half22float2(h2[q]);
                t[2 * q]     = f2tf32(f.x);
                t[2 * q + 1] = f2tf32(f.y);
            }
            float* dstp = Xs + r * GS + c8 * 8;
            *(uint4*)(dstp)     = *(uint4*)&t[0];
            *(uint4*)(dstp + 4) = *(uint4*)&t[4];
        }
    } else {
        const float4* X4 = (const float4*)Xv;
        #pragma unroll
        for (int i = 0; i < 16; i++) {
            int idx = tid + (i << 7);           // 0..2047
            int r = idx >> 5, c4 = idx & 31;
            int gr = row0 + r;
            float4 v = make_float4(0.f, 0.f, 0.f, 0.f);
            if (gr < n) v = X4[(size_t)gr * 32 + c4];
            uint4 t = make_uint4(f2tf32(v.x), f2tf32(v.y), f2tf32(v.z), f2tf32(v.w));
            *(uint4*)(Xs + r * GS + c4 * 4) = t;
        }
    }
    __syncthreads();

    const int wid  = tid >> 5;
    const int lane = tid & 31;
    const int g = lane >> 2;       // group row 0..7
    const int t = lane & 3;        // thread-in-group 0..3
    const int m0 = (wid & 1) * 32;     // warp rows within CTA tile
    const int n0 = (wid >> 1) * 64;    // warp cols

    float acc[2][8][4];
    #pragma unroll
    for (int mt = 0; mt < 2; mt++)
        #pragma unroll
        for (int j = 0; j < 8; j++)
            #pragma unroll
            for (int q = 0; q < 4; q++) acc[mt][j][q] = 0.f;

    #pragma unroll
    for (int s = 0; s < 16; s++) {
        const int k0 = s << 3;
        uint32_t a[2][4];
        #pragma unroll
        for (int mt = 0; mt < 2; mt++) {
            const float* base = Xs + (m0 + mt * 16 + g) * GS + k0 + t;
            a[mt][0] = *(const uint32_t*)(base);
            a[mt][1] = *(const uint32_t*)(base + 8 * GS);
            a[mt][2] = *(const uint32_t*)(base + 4);
            a[mt][3] = *(const uint32_t*)(base + 8 * GS + 4);
        }
        #pragma unroll
        for (int j = 0; j < 8; j++) {
            const float* wb = Ws + (n0 + j * 8 + g) * GS + k0 + t;
            uint32_t b0 = *(const uint32_t*)(wb);
            uint32_t b1 = *(const uint32_t*)(wb + 4);
            #pragma unroll
            for (int mt = 0; mt < 2; mt++) {
                asm volatile(
                    "mma.sync.aligned.m16n8k8.row.col.f32.tf32.tf32.f32 "
                    "{%0,%1,%2,%3}, {%4,%5,%6,%7}, {%8,%9}, {%0,%1,%2,%3};"
                    : "+f"(acc[mt][j][0]), "+f"(acc[mt][j][1]),
                      "+f"(acc[mt][j][2]), "+f"(acc[mt][j][3])
                    : "r"(a[mt][0]), "r"(a[mt][1]), "r"(a[mt][2]), "r"(a[mt][3]),
                      "r"(b0), "r"(b1));
            }
        }
    }

    // ---- epilogue: half2 stores. c0/c1 at (g, 2t), c2/c3 at (g+8, 2t) ----
    #pragma unroll
    for (int mt = 0; mt < 2; mt++) {
        int r_lo = row0 + m0 + mt * 16 + g;
        int r_hi = r_lo + 8;
        #pragma unroll
        for (int j = 0; j < 8; j++) {
            int c = n0 + j * 8 + 2 * t;
            float2 bv = *(const float2*)&bias[c];
            if (r_lo < n) {
                __half2 o = __floats2half2_rn(acc[mt][j][0] + bv.x,
                                              acc[mt][j][1] + bv.y);
                *(__half2*)(Y + (size_t)r_lo * HD + c) = o;
            }
            if (r_hi < n) {
                __half2 o = __floats2half2_rn(acc[mt][j][2] + bv.x,
                                              acc[mt][j][3] + bv.y);
                *(__half2*)(Y + (size_t)r_hi * HD + c) = o;
            }
        }
    }
}

// ---------------- gather: out[v] = relu(mean_{e->v} xw[src(e)])  (fp16 I/O) --
// One warp per node. Lane handles 4 cols (one uint2 = 4 halfs). Row = 256B.
__global__ void __launch_bounds__(256) gather_mean_relu(
    const __half* __restrict__ xw, const int* __restrict__ rp,
    const int* __restrict__ esrc, __half* __restrict__ out, int n)
{
    int gw = (blockIdx.x * blockDim.x + threadIdx.x) >> 5;
    if (gw >= n) return;
    int lane = threadIdx.x & 31;
    int a = __ldg(&rp[gw]);
    int b = __ldg(&rp[gw + 1]);

    float4 acc = make_float4(0.f, 0.f, 0.f, 0.f);
    const uint2* xw2 = (const uint2*)xw;          // row = 32 uint2
    int e = a;
    for (; e + 4 <= b; e += 4) {
        int s0 = __ldg(&esrc[e]);
        int s1 = __ldg(&esrc[e + 1]);
        int s2 = __ldg(&esrc[e + 2]);
        int s3 = __ldg(&esrc[e + 3]);
        uint2 u0 = __ldg(xw2 + (size_t)s0 * 32 + lane);
        uint2 u1 = __ldg(xw2 + (size_t)s1 * 32 + lane);
        uint2 u2 = __ldg(xw2 + (size_t)s2 * 32 + lane);
        uint2 u3 = __ldg(xw2 + (size_t)s3 * 32 + lane);
        #pragma unroll
        for (int q = 0; q < 4; q++) {
            uint2 u = (q == 0) ? u0 : (q == 1) ? u1 : (q == 2) ? u2 : u3;
            float2 lo = __half22float2(*(__half2*)&u.x);
            float2 hi = __half22float2(*(__half2*)&u.y);
            acc.x += lo.x; acc.y += lo.y; acc.z += hi.x; acc.w += hi.y;
        }
    }
    for (; e < b; e++) {
        int s = __ldg(&esrc[e]);
        uint2 u = __ldg(xw2 + (size_t)s * 32 + lane);
        float2 lo = __half22float2(*(__half2*)&u.x);
        float2 hi = __half22float2(*(__half2*)&u.y);
        acc.x += lo.x; acc.y += lo.y; acc.z += hi.x; acc.w += hi.y;
    }

    float inv = (b > a) ? 1.0f / (float)(b - a) : 0.0f;
    __half2 o0 = __floats2half2_rn(fmaxf(acc.x * inv, 0.f), fmaxf(acc.y * inv, 0.f));
    __half2 o1 = __floats2half2_rn(fmaxf(acc.z * inv, 0.f), fmaxf(acc.w * inv, 0.f));
    uint2 ou;
    *(__half2*)&ou.x = o0;
    *(__half2*)&ou.y = o1;
    ((uint2*)out)[(size_t)gw * 32 + lane] = ou;
}

// ---------------- segment_max pool (batch is sorted, h is fp16) --------------
__global__ void __launch_bounds__(128) pool_kernel(
    const __half* __restrict__ h, const int* __restrict__ batch,
    float* __restrict__ pool, int n)
{
    const int NPB = 128;
    int n0 = blockIdx.x * NPB;
    if (n0 >= n) return;
    int nend = min(n0 + NPB, n);
    int c = threadIdx.x;
    int curb = batch[n0];
    float m = 0.0f;
    for (int nn = n0; nn < nend; nn++) {
        int b = batch[nn];
        if (b != curb) {
            atomicMax((int*)&pool[curb * HD + c], __float_as_int(m));
            m = 0.0f;
            curb = b;
        }
        m = fmaxf(m, __half2float(h[(size_t)nn * HD + c]));
    }
    atomicMax((int*)&pool[curb * HD + c], __float_as_int(m));
}

// ---------------- FC head ----------------------------------------------------
__global__ void __launch_bounds__(128) fc1_kernel(
    const float* __restrict__ pool, const float* __restrict__ Wf1,
    const float* __restrict__ bf1, float* __restrict__ z)
{
    __shared__ float gv[HD];
    int g = blockIdx.x;
    gv[threadIdx.x] = pool[g * HD + threadIdx.x];
    __syncthreads();
    const float* w = Wf1 + threadIdx.x * HD;
    float acc = 0.f;
    #pragma unroll 16
    for (int k = 0; k < HD; k++) acc += gv[k] * w[k];
    z[g * HD + threadIdx.x] = fmaxf(acc + bf1[threadIdx.x], 0.f);
}

__global__ void __launch_bounds__(64) fc2_kernel(
    const float* __restrict__ z, const float* __restrict__ Wf2,
    const float* __restrict__ bf2, float* __restrict__ out)
{
    int g = threadIdx.x;
    if (g >= GNUM) return;
    float a0 = bf2[0], a1 = bf2[1];
    #pragma unroll 16
    for (int k = 0; k < HD; k++) {
        float v = z[g * HD + k];
        a0 += v * Wf2[k];
        a1 += v * Wf2[HD + k];
    }
    float m   = fmaxf(a0, a1);
    float lse = m + logf(expf(a0 - m) + expf(a1 - m));
    out[g * 2 + 0] = a0 - lse;
    out[g * 2 + 1] = a1 - lse;
}

// ---------------- launch -----------------------------------------------------
extern "C" void kernel_launch(void* const* d_in, const int* in_sizes, int n_in,
                              void* d_out, int out_size)
{
    const float* x     = (const float*)d_in[0];
    const int*   ei    = (const int*)d_in[1];
    const int*   batch = (const int*)d_in[2];
    const float* W1    = (const float*)d_in[3];
    const float* b1    = (const float*)d_in[4];
    const float* W2    = (const float*)d_in[5];
    const float* b2    = (const float*)d_in[6];
    const float* Wf1   = (const float*)d_in[7];
    const float* bf1   = (const float*)d_in[8];
    const float* Wf2   = (const float*)d_in[9];
    const float* bf2   = (const float*)d_in[10];

    const int n = in_sizes[0] / HD;        // 100000
    const int E = in_sizes[1] / 2;         // 1600000
    const int* src = ei;
    const int* dst = ei + E;

    __half *bufA, *bufB;
    float *pool, *zb;
    int *deg, *local, *rowptr, *cursor, *esrc, *part;
    cudaGetSymbolAddress((void**)&bufA,   g_bufA);
    cudaGetSymbolAddress((void**)&bufB,   g_bufB);
    cudaGetSymbolAddress((void**)&deg,    g_deg);
    cudaGetSymbolAddress((void**)&local,  g_local);
    cudaGetSymbolAddress((void**)&rowptr, g_rowptr);
    cudaGetSymbolAddress((void**)&cursor, g_cursor);
    cudaGetSymbolAddress((void**)&esrc,   g_esrc);
    cudaGetSymbolAddress((void**)&part,   g_part);
    cudaGetSymbolAddress((void**)&pool,   g_pool);
    cudaGetSymbolAddress((void**)&zb,     g_zbuf);

    cudaFuncSetAttribute(gemm_mma<false>,
                         cudaFuncAttributeMaxDynamicSharedMemorySize, GEMM_SMEM);
    cudaFuncSetAttribute(gemm_mma<true>,
                         cudaFuncAttributeMaxDynamicSharedMemorySize, GEMM_SMEM);

    const int gemm_blocks   = (n + 63) / 64;
    const int gather_blocks = (n * 32 + 255) / 256;   // warp per node
    const int eblocks       = (E + 255) / 256;
    const int nscan_blocks  = (n + SBLK - 1) / SBLK;  // 391

    // ---- CSR build (once; reused by both layers) ----
    zero_f4<<<(n / 4 + 255) / 256, 256>>>((float4*)deg, n / 4);
    hist_kernel<<<eblocks, 256>>>(dst, deg, E);
    scan_blocks<<<nscan_blocks, SBLK>>>(deg, part, local, n);
    scan_partials<<<1, 512>>>(part, nscan_blocks);
    scan_finalize<<<(n + 255) / 256, 256>>>(local, part, rowptr, cursor, n, E);
    fill_csr<<<eblocks, 256>>>(src, dst, cursor, esrc, E);

    // ---- layer 1 ----
    gemm_mma<false><<<gemm_blocks, 128, GEMM_SMEM>>>(x, W1, b1, bufA, n);
    gather_mean_relu<<<gather_blocks, 256>>>(bufA, rowptr, esrc, bufB, n);

    // ---- layer 2 ----
    gemm_mma<true><<<gemm_blocks, 128, GEMM_SMEM>>>(bufB, W2, b2, bufA, n);
    gather_mean_relu<<<gather_blocks, 256>>>(bufA, rowptr, esrc, bufB, n);

    // ---- pool + head ----
    zero_f4<<<(GNUM * HD / 4 + 255) / 256, 256>>>((float4*)pool, GNUM * HD / 4);
    pool_kernel<<<(n + 127) / 128, 128>>>(bufB, batch, pool, n);
    fc1_kernel<<<GNUM, 128>>>(pool, Wf1, bf1, zb);
    fc2_kernel<<<1, 64>>>(zb, Wf2, bf2, (float*)d_out);
}

// round 12
// speedup vs baseline: 1.1601x; 1.0070x over previous
#include <cuda_runtime.h>
#include <cuda_fp16.h>
#include <math.h>
#include <stdint.h>

#define NMAX 100000
#define EMAX 1600000
#define HD 128
#define GNUM 64

// ---------------- scratch (device globals: no allocation APIs allowed) ------
__device__ float g_bufA[(size_t)NMAX * HD / 2];   // used as __half[N*HD]
__device__ float g_bufB[(size_t)NMAX * HD / 2];   // used as __half[N*HD]
__device__ int   g_deg[NMAX];
__device__ int   g_local[NMAX];
__device__ int   g_rowptr[NMAX + 1];
__device__ int   g_cursor[NMAX];
__device__ int   g_esrc[EMAX];
__device__ int   g_part[512];
__device__ float g_pool[GNUM * HD];
__device__ float g_zbuf[GNUM * HD];

// ---------------- zero fill --------------------------------------------------
__global__ void zero_f4(float4* __restrict__ p, int n4) {
    int i = blockIdx.x * blockDim.x + threadIdx.x;
    if (i < n4) p[i] = make_float4(0.f, 0.f, 0.f, 0.f);
}

// ---------------- CSR build --------------------------------------------------
__global__ void __launch_bounds__(256) hist_kernel(
    const int* __restrict__ dst, int* __restrict__ deg, int E)
{
    int e = blockIdx.x * blockDim.x + threadIdx.x;
    if (e < E) atomicAdd(&deg[dst[e]], 1);
}

#define SBLK 256
__global__ void __launch_bounds__(SBLK) scan_blocks(
    const int* __restrict__ deg, int* __restrict__ bsum,
    int* __restrict__ local, int n)
{
    __shared__ int sm[SBLK];
    int i = blockIdx.x * SBLK + threadIdx.x;
    int v = (i < n) ? deg[i] : 0;
    sm[threadIdx.x] = v;
    __syncthreads();
    #pragma unroll
    for (int off = 1; off < SBLK; off <<= 1) {
        int t = (threadIdx.x >= off) ? sm[threadIdx.x - off] : 0;
        __syncthreads();
        sm[threadIdx.x] += t;
        __syncthreads();
    }
    if (i < n) local[i] = sm[threadIdx.x] - v;            // exclusive local
    if (threadIdx.x == SBLK - 1) bsum[blockIdx.x] = sm[SBLK - 1];
}

__global__ void __launch_bounds__(512) scan_partials(int* __restrict__ bsum, int nb)
{
    __shared__ int sm[512];
    int v = (threadIdx.x < nb) ? bsum[threadIdx.x] : 0;
    sm[threadIdx.x] = v;
    __syncthreads();
    #pragma unroll
    for (int off = 1; off < 512; off <<= 1) {
        int t = (threadIdx.x >= off) ? sm[threadIdx.x - off] : 0;
        __syncthreads();
        sm[threadIdx.x] += t;
        __syncthreads();
    }
    if (threadIdx.x < nb) bsum[threadIdx.x] = sm[threadIdx.x] - v;  // exclusive
}

__global__ void __launch_bounds__(256) scan_finalize(
    const int* __restrict__ local, const int* __restrict__ bsum,
    int* __restrict__ rowptr, int* __restrict__ cursor, int n, int E)
{
    int i = blockIdx.x * blockDim.x + threadIdx.x;
    if (i < n) {
        int v = local[i] + bsum[i / SBLK];
        rowptr[i] = v;
        cursor[i] = v;
    }
    if (i == 0) rowptr[n] = E;
}

__global__ void __launch_bounds__(256) fill_csr(
    const int* __restrict__ src, const int* __restrict__ dst,
    int* __restrict__ cursor, int* __restrict__ esrc, int E)
{
    int e = blockIdx.x * blockDim.x + threadIdx.x;
    if (e < E) {
        int pos = atomicAdd(&cursor[dst[e]], 1);
        esrc[pos] = src[e];
    }
}

// ============================================================================
// tf32 mma.sync GEMM: Y = X @ W^T + bias.  X:[n,128] (f32 or f16), W f32.
// Output: __half [n,128].
// CTA: 64 rows x 128 cols, 128 threads (4 warps), warp tile 32x64.
// ============================================================================
#define GS 132                              // smem row stride (floats)
#define GEMM_SMEM ((128 * GS + 64 * GS) * 4)   // W tile + X tile = 101376 B

__device__ __forceinline__ uint32_t f2tf32(float f) {
    uint32_t u;
    asm("cvt.rna.tf32.f32 %0, %1;" : "=r"(u) : "f"(f));
    return u;
}

template<bool HALF_IN>
__global__ void __launch_bounds__(128, 2) gemm_mma(
    const void* __restrict__ Xv, const float* __restrict__ W,
    const float* __restrict__ bias, __half* __restrict__ Y, int n)
{
    extern __shared__ float sm[];
    float* Ws = sm;                 // [128][GS]  (row n of W = output col n)
    float* Xs = sm + 128 * GS;      // [64][GS]
    const int tid  = threadIdx.x;
    const int row0 = blockIdx.x * 64;

    // ---- load W tile (tf32-rounded): 128x32 float4 ----
    const float4* W4 = (const float4*)W;
    #pragma unroll
    for (int i = 0; i < 32; i++) {
        int idx = tid + (i << 7);           // 0..4095
        int r = idx >> 5, c4 = idx & 31;
        float4 v = W4[idx];
        uint4 t = make_uint4(f2tf32(v.x), f2tf32(v.y), f2tf32(v.z), f2tf32(v.w));
        *(uint4*)(Ws + r * GS + c4 * 4) = t;
    }
    // ---- load X tile (tf32-rounded, zero-padded) ----
    if (HALF_IN) {
        const uint4* X8 = (const uint4*)Xv;       // 16B = 8 halfs
        #pragma unroll
        for (int i = 0; i < 8; i++) {
            int idx = tid + (i << 7);             // 0..1023
            int r = idx >> 4, c8 = idx & 15;      // row, 8-col chunk
            int gr = row0 + r;
            uint4 u = make_uint4(0, 0, 0, 0);
            if (gr < n) u = X8[(size_t)gr * 16 + c8];
            const __half2* h2 = (const __half2*)&u;
            uint32_t t[8];
            #pragma unroll
            for (int q = 0; q < 4; q++) {
                float2 f = __half22float2(h2[q]);
                t[2 * q]     = f2tf32(f.x);
                t[2 * q + 1] = f2tf32(f.y);
            }
            float* dstp = Xs + r * GS + c8 * 8;
            *(uint4*)(dstp)     = *(uint4*)&t[0];
            *(uint4*)(dstp + 4) = *(uint4*)&t[4];
        }
    } else {
        const float4* X4 = (const float4*)Xv;
        #pragma unroll
        for (int i = 0; i < 16; i++) {
            int idx = tid + (i << 7);           // 0..2047
            int r = idx >> 5, c4 = idx & 31;
            int gr = row0 + r;
            float4 v = make_float4(0.f, 0.f, 0.f, 0.f);
            if (gr < n) v = X4[(size_t)gr * 32 + c4];
            uint4 t = make_uint4(f2tf32(v.x), f2tf32(v.y), f2tf32(v.z), f2tf32(v.w));
            *(uint4*)(Xs + r * GS + c4 * 4) = t;
        }
    }
    __syncthreads();

    const int wid  = tid >> 5;
    const int lane = tid & 31;
    const int g = lane >> 2;       // group row 0..7
    const int t = lane & 3;        // thread-in-group 0..3
    const int m0 = (wid & 1) * 32;     // warp rows within CTA tile
    const int n0 = (wid >> 1) * 64;    // warp cols

    float acc[2][8][4];
    #pragma unroll
    for (int mt = 0; mt < 2; mt++)
        #pragma unroll
        for (int j = 0; j < 8; j++)
            #pragma unroll
            for (int q = 0; q < 4; q++) acc[mt][j][q] = 0.f;

    #pragma unroll
    for (int s = 0; s < 16; s++) {
        const int k0 = s << 3;
        uint32_t a[2][4];
        #pragma unroll
        for (int mt = 0; mt < 2; mt++) {
            const float* base = Xs + (m0 + mt * 16 + g) * GS + k0 + t;
            a[mt][0] = *(const uint32_t*)(base);
            a[mt][1] = *(const uint32_t*)(base + 8 * GS);
            a[mt][2] = *(const uint32_t*)(base + 4);
            a[mt][3] = *(const uint32_t*)(base + 8 * GS + 4);
        }
        #pragma unroll
        for (int j = 0; j < 8; j++) {
            const float* wb = Ws + (n0 + j * 8 + g) * GS + k0 + t;
            uint32_t b0 = *(const uint32_t*)(wb);
            uint32_t b1 = *(const uint32_t*)(wb + 4);
            #pragma unroll
            for (int mt = 0; mt < 2; mt++) {
                asm volatile(
                    "mma.sync.aligned.m16n8k8.row.col.f32.tf32.tf32.f32 "
                    "{%0,%1,%2,%3}, {%4,%5,%6,%7}, {%8,%9}, {%0,%1,%2,%3};"
                    : "+f"(acc[mt][j][0]), "+f"(acc[mt][j][1]),
                      "+f"(acc[mt][j][2]), "+f"(acc[mt][j][3])
                    : "r"(a[mt][0]), "r"(a[mt][1]), "r"(a[mt][2]), "r"(a[mt][3]),
                      "r"(b0), "r"(b1));
            }
        }
    }

    // ---- epilogue: half2 stores. c0/c1 at (g, 2t), c2/c3 at (g+8, 2t) ----
    #pragma unroll
    for (int mt = 0; mt < 2; mt++) {
        int r_lo = row0 + m0 + mt * 16 + g;
        int r_hi = r_lo + 8;
        #pragma unroll
        for (int j = 0; j < 8; j++) {
            int c = n0 + j * 8 + 2 * t;
            float2 bv = *(const float2*)&bias[c];
            if (r_lo < n) {
                __half2 o = __floats2half2_rn(acc[mt][j][0] + bv.x,
                                              acc[mt][j][1] + bv.y);
                *(__half2*)(Y + (size_t)r_lo * HD + c) = o;
            }
            if (r_hi < n) {
                __half2 o = __floats2half2_rn(acc[mt][j][2] + bv.x,
                                              acc[mt][j][3] + bv.y);
                *(__half2*)(Y + (size_t)r_hi * HD + c) = o;
            }
        }
    }
}

// ---------------- gather: out[v] = relu(mean_{e->v} xw[src(e)])  (fp16 I/O) --
// One warp per node. Lane handles 4 cols (one uint2 = 4 halfs). Row = 256B.
__global__ void __launch_bounds__(256) gather_mean_relu(
    const __half* __restrict__ xw, const int* __restrict__ rp,
    const int* __restrict__ esrc, __half* __restrict__ out, int n)
{
    int gw = (blockIdx.x * blockDim.x + threadIdx.x) >> 5;
    if (gw >= n) return;
    int lane = threadIdx.x & 31;
    int a = __ldg(&rp[gw]);
    int b = __ldg(&rp[gw + 1]);

    float4 acc = make_float4(0.f, 0.f, 0.f, 0.f);
    const uint2* xw2 = (const uint2*)xw;          // row = 32 uint2
    int e = a;
    for (; e + 4 <= b; e += 4) {
        int s0 = __ldg(&esrc[e]);
        int s1 = __ldg(&esrc[e + 1]);
        int s2 = __ldg(&esrc[e + 2]);
        int s3 = __ldg(&esrc[e + 3]);
        uint2 u0 = __ldg(xw2 + (size_t)s0 * 32 + lane);
        uint2 u1 = __ldg(xw2 + (size_t)s1 * 32 + lane);
        uint2 u2 = __ldg(xw2 + (size_t)s2 * 32 + lane);
        uint2 u3 = __ldg(xw2 + (size_t)s3 * 32 + lane);
        #pragma unroll
        for (int q = 0; q < 4; q++) {
            uint2 u = (q == 0) ? u0 : (q == 1) ? u1 : (q == 2) ? u2 : u3;
            float2 lo = __half22float2(*(__half2*)&u.x);
            float2 hi = __half22float2(*(__half2*)&u.y);
            acc.x += lo.x; acc.y += lo.y; acc.z += hi.x; acc.w += hi.y;
        }
    }
    for (; e < b; e++) {
        int s = __ldg(&esrc[e]);
        uint2 u = __ldg(xw2 + (size_t)s * 32 + lane);
        float2 lo = __half22float2(*(__half2*)&u.x);
        float2 hi = __half22float2(*(__half2*)&u.y);
        acc.x += lo.x; acc.y += lo.y; acc.z += hi.x; acc.w += hi.y;
    }

    float inv = (b > a) ? 1.0f / (float)(b - a) : 0.0f;
    __half2 o0 = __floats2half2_rn(fmaxf(acc.x * inv, 0.f), fmaxf(acc.y * inv, 0.f));
    __half2 o1 = __floats2half2_rn(fmaxf(acc.z * inv, 0.f), fmaxf(acc.w * inv, 0.f));
    uint2 ou;
    *(__half2*)&ou.x = o0;
    *(__half2*)&ou.y = o1;
    ((uint2*)out)[(size_t)gw * 32 + lane] = ou;
}

// ---------------- segment_max pool (batch is sorted, h is fp16) --------------
__global__ void __launch_bounds__(128) pool_kernel(
    const __half* __restrict__ h, const int* __restrict__ batch,
    float* __restrict__ pool, int n)
{
    const int NPB = 128;
    int n0 = blockIdx.x * NPB;
    if (n0 >= n) return;
    int nend = min(n0 + NPB, n);
    int c = threadIdx.x;
    int curb = batch[n0];
    float m = 0.0f;
    for (int nn = n0; nn < nend; nn++) {
        int b = batch[nn];
        if (b != curb) {
            atomicMax((int*)&pool[curb * HD + c], __float_as_int(m));
            m = 0.0f;
            curb = b;
        }
        m = fmaxf(m, __half2float(h[(size_t)nn * HD + c]));
    }
    atomicMax((int*)&pool[curb * HD + c], __float_as_int(m));
}

// ---------------- FC head ----------------------------------------------------
__global__ void __launch_bounds__(128) fc1_kernel(
    const float* __restrict__ pool, const float* __restrict__ Wf1,
    const float* __restrict__ bf1, float* __restrict__ z)
{
    __shared__ float gv[HD];
    int g = blockIdx.x;
    gv[threadIdx.x] = pool[g * HD + threadIdx.x];
    __syncthreads();
    const float* w = Wf1 + threadIdx.x * HD;
    float acc = 0.f;
    #pragma unroll 16
    for (int k = 0; k < HD; k++) acc += gv[k] * w[k];
    z[g * HD + threadIdx.x] = fmaxf(acc + bf1[threadIdx.x], 0.f);
}

__global__ void __launch_bounds__(64) fc2_kernel(
    const float* __restrict__ z, const float* __restrict__ Wf2,
    const float* __restrict__ bf2, float* __restrict__ out)
{
    int g = threadIdx.x;
    if (g >= GNUM) return;
    float a0 = bf2[0], a1 = bf2[1];
    #pragma unroll 16
    for (int k = 0; k < HD; k++) {
        float v = z[g * HD + k];
        a0 += v * Wf2[k];
        a1 += v * Wf2[HD + k];
    }
    float m   = fmaxf(a0, a1);
    float lse = m + logf(expf(a0 - m) + expf(a1 - m));
    out[g * 2 + 0] = a0 - lse;
    out[g * 2 + 1] = a1 - lse;
}

// ---------------- launch -----------------------------------------------------
extern "C" void kernel_launch(void* const* d_in, const int* in_sizes, int n_in,
                              void* d_out, int out_size)
{
    const float* x     = (const float*)d_in[0];
    const int*   ei    = (const int*)d_in[1];
    const int*   batch = (const int*)d_in[2];
    const float* W1    = (const float*)d_in[3];
    const float* b1    = (const float*)d_in[4];
    const float* W2    = (const float*)d_in[5];
    const float* b2    = (const float*)d_in[6];
    const float* Wf1   = (const float*)d_in[7];
    const float* bf1   = (const float*)d_in[8];
    const float* Wf2   = (const float*)d_in[9];
    const float* bf2   = (const float*)d_in[10];

    const int n = in_sizes[0] / HD;        // 100000
    const int E = in_sizes[1] / 2;         // 1600000
    const int* src = ei;
    const int* dst = ei + E;

    __half *bufA, *bufB;
    float *pool, *zb;
    int *deg, *local, *rowptr, *cursor, *esrc, *part;
    cudaGetSymbolAddress((void**)&bufA,   g_bufA);
    cudaGetSymbolAddress((void**)&bufB,   g_bufB);
    cudaGetSymbolAddress((void**)&deg,    g_deg);
    cudaGetSymbolAddress((void**)&local,  g_local);
    cudaGetSymbolAddress((void**)&rowptr, g_rowptr);
    cudaGetSymbolAddress((void**)&cursor, g_cursor);
    cudaGetSymbolAddress((void**)&esrc,   g_esrc);
    cudaGetSymbolAddress((void**)&part,   g_part);
    cudaGetSymbolAddress((void**)&pool,   g_pool);
    cudaGetSymbolAddress((void**)&zb,     g_zbuf);

    cudaFuncSetAttribute(gemm_mma<false>,
                         cudaFuncAttributeMaxDynamicSharedMemorySize, GEMM_SMEM);
    cudaFuncSetAttribute(gemm_mma<true>,
                         cudaFuncAttributeMaxDynamicSharedMemorySize, GEMM_SMEM);

    const int gemm_blocks   = (n + 63) / 64;
    const int gather_blocks = (n * 32 + 255) / 256;   // warp per node
    const int eblocks       = (E + 255) / 256;
    const int nscan_blocks  = (n + SBLK - 1) / SBLK;  // 391

    // ---- CSR build (once; reused by both layers) ----
    zero_f4<<<(n / 4 + 255) / 256, 256>>>((float4*)deg, n / 4);
    hist_kernel<<<eblocks, 256>>>(dst, deg, E);
    scan_blocks<<<nscan_blocks, SBLK>>>(deg, part, local, n);
    scan_partials<<<1, 512>>>(part, nscan_blocks);
    scan_finalize<<<(n + 255) / 256, 256>>>(local, part, rowptr, cursor, n, E);
    fill_csr<<<eblocks, 256>>>(src, dst, cursor, esrc, E);

    // ---- layer 1 ----
    gemm_mma<false><<<gemm_blocks, 128, GEMM_SMEM>>>(x, W1, b1, bufA, n);
    gather_mean_relu<<<gather_blocks, 256>>>(bufA, rowptr, esrc, bufB, n);

    // ---- layer 2 ----
    gemm_mma<true><<<gemm_blocks, 128, GEMM_SMEM>>>(bufB, W2, b2, bufA, n);
    gather_mean_relu<<<gather_blocks, 256>>>(bufA, rowptr, esrc, bufB, n);

    // ---- pool + head ----
    zero_f4<<<(GNUM * HD / 4 + 255) / 256, 256>>>((float4*)pool, GNUM * HD / 4);
    pool_kernel<<<(n + 127) / 128, 128>>>(bufB, batch, pool, n);
    fc1_kernel<<<GNUM, 128>>>(pool, Wf1, bf1, zb);
    fc2_kernel<<<1, 64>>>(zb, Wf2, bf2, (float*)d_out);
}